// round 1
// baseline (speedup 1.0000x reference)
#include <cuda_runtime.h>

#define HID 64
#define EXT 32
#define TE 32   // edges per tile
#define TN 32   // nodes per tile
#define MAX_NODES 50000

// Scratch: per-node precomputed partials P = h @ W1[0:64], Q = h @ W1[128:192]
__device__ float g_P[MAX_NODES * HID];
__device__ float g_Q[MAX_NODES * HID];

__device__ __forceinline__ void fma4(float4& a, float s, const float4 w) {
    a.x = fmaf(s, w.x, a.x);
    a.y = fmaf(s, w.y, a.y);
    a.z = fmaf(s, w.z, a.z);
    a.w = fmaf(s, w.w, a.w);
}

// ---------------------------------------------------------------------------
// Kernel 1: per-node precompute P = h @ W1a, Q = h @ W1c
// ---------------------------------------------------------------------------
__global__ __launch_bounds__(256) void node_pre(const float* __restrict__ h,
                                                const float* __restrict__ W1,
                                                int n_nodes)
{
    __shared__ float Wa[HID * HID];
    __shared__ float Wc[HID * HID];
    __shared__ float hs[TN][HID];

    for (int i = threadIdx.x; i < HID * HID; i += 256) {
        Wa[i] = W1[i];                    // rows 0..63   (src part)
        Wc[i] = W1[2 * HID * HID + i];    // rows 128..191 (dst part)
    }

    const int tx = threadIdx.x & 15;
    const int ty = threadIdx.x >> 4;     // 0..15
    const int j0 = tx * 4;
    const int ntiles = (n_nodes + TN - 1) / TN;

    for (int tile = blockIdx.x; tile < ntiles; tile += gridDim.x) {
        const int base = tile * TN;
        __syncthreads();   // weights ready (1st iter) / hs consumers done (later iters)
        for (int i = threadIdx.x; i < TN * (HID / 4); i += 256) {
            int r = i >> 4, c = (i & 15) * 4;
            int node = base + r;
            float4 v = make_float4(0.f, 0.f, 0.f, 0.f);
            if (node < n_nodes) v = *(const float4*)(h + (size_t)node * HID + c);
            *(float4*)(&hs[r][c]) = v;
        }
        __syncthreads();

        float4 aP[2], aQ[2];
        #pragma unroll
        for (int rr = 0; rr < 2; rr++) {
            aP[rr] = make_float4(0.f, 0.f, 0.f, 0.f);
            aQ[rr] = make_float4(0.f, 0.f, 0.f, 0.f);
        }
        #pragma unroll 4
        for (int k = 0; k < HID; k++) {
            float4 wa = *(const float4*)(Wa + k * HID + j0);
            float4 wc = *(const float4*)(Wc + k * HID + j0);
            #pragma unroll
            for (int rr = 0; rr < 2; rr++) {
                float s = hs[ty + rr * 16][k];
                fma4(aP[rr], s, wa);
                fma4(aQ[rr], s, wc);
            }
        }
        #pragma unroll
        for (int rr = 0; rr < 2; rr++) {
            int node = base + ty + rr * 16;
            if (node < n_nodes) {
                *(float4*)(g_P + (size_t)node * HID + j0) = aP[rr];
                *(float4*)(g_Q + (size_t)node * HID + j0) = aQ[rr];
            }
        }
    }
}

// ---------------------------------------------------------------------------
// Kernel 2: per-edge  x = P[src]+Q[dst]+b1 + e_h@W1b ;  out = relu(x@W2a + ext@W2b + b2)
// Dynamic smem layout (floats):
//   W1b[4096] W2a[4096] W2b[2048] b1s[64] b2s[64] ehs[TE*64] exts[TE*32] xs[TE*64]
//   then int srcs[TE], dsts[TE]
// ---------------------------------------------------------------------------
#define EDGE_SMEM_FLOATS (4096 + 4096 + 2048 + 64 + 64 + TE * 64 + TE * 32 + TE * 64)
#define EDGE_SMEM_BYTES  (EDGE_SMEM_FLOATS * 4 + TE * 2 * 4)

__global__ __launch_bounds__(256) void edge_kernel(
    const float* __restrict__ e_h,
    const float* __restrict__ ext,
    const float* __restrict__ W1,
    const float* __restrict__ b1,
    const float* __restrict__ W2,
    const float* __restrict__ b2,
    const int* __restrict__ src,
    const int* __restrict__ dst,
    float* __restrict__ out,
    int n_edges)
{
    extern __shared__ float smem[];
    float* W1b  = smem;
    float* W2a  = W1b + 4096;
    float* W2b  = W2a + 4096;
    float* b1s  = W2b + 2048;
    float* b2s  = b1s + 64;
    float* ehs  = b2s + 64;            // [TE][64]
    float* exts = ehs + TE * 64;       // [TE][32]
    float* xs   = exts + TE * 32;      // [TE][64]
    int*   srcs = (int*)(xs + TE * 64);
    int*   dsts = srcs + TE;

    for (int i = threadIdx.x; i < HID * HID; i += 256) {
        W1b[i] = W1[HID * HID + i];   // rows 64..127 of W1
        W2a[i] = W2[i];               // rows 0..63 of W2
    }
    for (int i = threadIdx.x; i < EXT * HID; i += 256)
        W2b[i] = W2[HID * HID + i];   // rows 64..95 of W2
    if (threadIdx.x < 64) {
        b1s[threadIdx.x] = b1[threadIdx.x];
        b2s[threadIdx.x] = b2[threadIdx.x];
    }

    const int tx = threadIdx.x & 15;
    const int ty = threadIdx.x >> 4;    // 0..15
    const int j0 = tx * 4;
    const int ntiles = (n_edges + TE - 1) / TE;

    for (int tile = blockIdx.x; tile < ntiles; tile += gridDim.x) {
        const int base = tile * TE;
        __syncthreads();  // weights ready / previous tile fully consumed

        // stage e_h tile: TE*64 floats
        for (int i = threadIdx.x; i < TE * (HID / 4); i += 256) {
            int r = i >> 4, c = (i & 15) * 4;
            int e = base + r;
            float4 v = make_float4(0.f, 0.f, 0.f, 0.f);
            if (e < n_edges) v = *(const float4*)(e_h + (size_t)e * HID + c);
            *(float4*)(ehs + r * HID + c) = v;
        }
        // stage ext tile: TE*32 floats
        for (int i = threadIdx.x; i < TE * (EXT / 4); i += 256) {
            int r = i >> 3, c = (i & 7) * 4;
            int e = base + r;
            float4 v = make_float4(0.f, 0.f, 0.f, 0.f);
            if (e < n_edges) v = *(const float4*)(ext + (size_t)e * EXT + c);
            *(float4*)(exts + r * EXT + c) = v;
        }
        if (threadIdx.x < TE) {
            int e = base + threadIdx.x;
            srcs[threadIdx.x] = (e < n_edges) ? src[e] : 0;
            dsts[threadIdx.x] = (e < n_edges) ? dst[e] : 0;
        }
        __syncthreads();

        // ---- layer 1 ----
        float4 a[2];
        #pragma unroll
        for (int rr = 0; rr < 2; rr++) {
            int r = ty + rr * 16;
            float4 p = *(const float4*)(g_P + (size_t)srcs[r] * HID + j0);
            float4 q = *(const float4*)(g_Q + (size_t)dsts[r] * HID + j0);
            a[rr].x = p.x + q.x + b1s[j0 + 0];
            a[rr].y = p.y + q.y + b1s[j0 + 1];
            a[rr].z = p.z + q.z + b1s[j0 + 2];
            a[rr].w = p.w + q.w + b1s[j0 + 3];
        }
        #pragma unroll 4
        for (int k = 0; k < HID; k++) {
            float4 w = *(const float4*)(W1b + k * HID + j0);
            #pragma unroll
            for (int rr = 0; rr < 2; rr++)
                fma4(a[rr], ehs[(ty + rr * 16) * HID + k], w);
        }
        #pragma unroll
        for (int rr = 0; rr < 2; rr++)
            *(float4*)(xs + (ty + rr * 16) * HID + j0) = a[rr];
        __syncthreads();

        // ---- layer 2 ----
        float4 o[2];
        #pragma unroll
        for (int rr = 0; rr < 2; rr++) {
            o[rr].x = b2s[j0 + 0];
            o[rr].y = b2s[j0 + 1];
            o[rr].z = b2s[j0 + 2];
            o[rr].w = b2s[j0 + 3];
        }
        #pragma unroll 4
        for (int k = 0; k < HID; k++) {
            float4 w = *(const float4*)(W2a + k * HID + j0);
            #pragma unroll
            for (int rr = 0; rr < 2; rr++)
                fma4(o[rr], xs[(ty + rr * 16) * HID + k], w);
        }
        #pragma unroll 4
        for (int k = 0; k < EXT; k++) {
            float4 w = *(const float4*)(W2b + k * HID + j0);
            #pragma unroll
            for (int rr = 0; rr < 2; rr++)
                fma4(o[rr], exts[(ty + rr * 16) * EXT + k], w);
        }
        #pragma unroll
        for (int rr = 0; rr < 2; rr++) {
            int e = base + ty + rr * 16;
            if (e < n_edges) {
                float4 v;
                v.x = fmaxf(o[rr].x, 0.f);
                v.y = fmaxf(o[rr].y, 0.f);
                v.z = fmaxf(o[rr].z, 0.f);
                v.w = fmaxf(o[rr].w, 0.f);
                *(float4*)(out + (size_t)e * HID + j0) = v;
            }
        }
    }
}

// ---------------------------------------------------------------------------
extern "C" void kernel_launch(void* const* d_in, const int* in_sizes, int n_in,
                              void* d_out, int out_size)
{
    const float* h   = (const float*)d_in[0];
    const float* e_h = (const float*)d_in[1];
    const float* ext = (const float*)d_in[2];
    const float* W1  = (const float*)d_in[3];
    const float* b1  = (const float*)d_in[4];
    const float* W2  = (const float*)d_in[5];
    const float* b2  = (const float*)d_in[6];
    const int*   src = (const int*)d_in[7];
    const int*   dst = (const int*)d_in[8];
    float* out = (float*)d_out;

    int n_nodes = in_sizes[0] / HID;
    int n_edges = in_sizes[7];

    cudaFuncSetAttribute(edge_kernel,
                         cudaFuncAttributeMaxDynamicSharedMemorySize,
                         EDGE_SMEM_BYTES);

    int node_tiles = (n_nodes + TN - 1) / TN;
    int grid1 = node_tiles < 592 ? node_tiles : 592;
    node_pre<<<grid1, 256>>>(h, W1, n_nodes);

    int edge_tiles = (n_edges + TE - 1) / TE;
    int grid2 = edge_tiles < 444 ? edge_tiles : 444;
    edge_kernel<<<grid2, 256, EDGE_SMEM_BYTES>>>(e_h, ext, W1, b1, W2, b2,
                                                 src, dst, out, n_edges);
}

// round 2
// speedup vs baseline: 1.8485x; 1.8485x over previous
#include <cuda_runtime.h>

#define HID 64
#define EXT 32
#define TE 64
#define TN 64
#define MAX_NODES 50000

// Per-node precomputed partials (already multiplied through W2a):
//   g_P[n] = h[n] @ (W1a @ W2a),  g_Q[n] = h[n] @ (W1c @ W2a)
__device__ float g_P[MAX_NODES * HID];
__device__ float g_Q[MAX_NODES * HID];
// Fused weights
__device__ float g_W12[HID * HID];   // W1b @ W2a
__device__ float g_Wa2[HID * HID];   // W1a @ W2a
__device__ float g_Wc2[HID * HID];   // W1c @ W2a
__device__ float g_b12[HID];         // b1 @ W2a + b2

typedef unsigned long long u64;

__device__ __forceinline__ u64 pk2(float x, float y) {
    u64 r; asm("mov.b64 %0,{%1,%2};" : "=l"(r) : "f"(x), "f"(y)); return r;
}
__device__ __forceinline__ float2 up2(u64 v) {
    float2 f; asm("mov.b64 {%0,%1},%2;" : "=f"(f.x), "=f"(f.y) : "l"(v)); return f;
}
__device__ __forceinline__ void ffma2(u64& d, u64 a, u64 b) {
    asm("fma.rn.f32x2 %0,%1,%2,%0;" : "+l"(d) : "l"(a), "l"(b));
}

// ---------------------------------------------------------------------------
// Kernel 0: fold W2a into W1 parts and biases.
// ---------------------------------------------------------------------------
__global__ __launch_bounds__(256) void combo_kernel(
    const float* __restrict__ W1, const float* __restrict__ b1,
    const float* __restrict__ W2, const float* __restrict__ b2)
{
    __shared__ float W2s[HID * HID];
    for (int i = threadIdx.x; i < HID * HID; i += 256) W2s[i] = W2[i];
    __syncthreads();

    int b = blockIdx.x;
    if (b < 12) {
        int mat = b >> 2;
        const float* srcW = W1 + (size_t)mat * HID * HID;
        float* dstW = (mat == 0) ? g_Wa2 : (mat == 1) ? g_W12 : g_Wc2;
        int row = (b & 3) * 16 + (threadIdx.x >> 4);
        int c0 = (threadIdx.x & 15) * 4;
        float4 a = make_float4(0.f, 0.f, 0.f, 0.f);
        #pragma unroll 8
        for (int k = 0; k < HID; k++) {
            float s = srcW[row * HID + k];
            float4 w = *(const float4*)(W2s + k * HID + c0);
            a.x = fmaf(s, w.x, a.x); a.y = fmaf(s, w.y, a.y);
            a.z = fmaf(s, w.z, a.z); a.w = fmaf(s, w.w, a.w);
        }
        *(float4*)(dstW + row * HID + c0) = a;
    } else {
        if (threadIdx.x < HID) {
            int o = threadIdx.x;
            float acc = b2[o];
            #pragma unroll 8
            for (int k = 0; k < HID; k++)
                acc = fmaf(b1[k], W2s[k * HID + o], acc);
            g_b12[o] = acc;
        }
    }
}

// ---------------------------------------------------------------------------
// Kernel 1: per-node  P = h @ Wa2,  Q = h @ Wc2
// ---------------------------------------------------------------------------
#define NODE_SMEM_BYTES ((4096 + 4096 + HID * TN) * 4)

__global__ __launch_bounds__(256) void node_pre(const float* __restrict__ h,
                                                int n_nodes)
{
    extern __shared__ float sm[];
    float* Wa  = sm;
    float* Wc  = Wa + 4096;
    float* hst = Wc + 4096;            // [k][r], stride TN

    for (int i = threadIdx.x; i < HID * HID; i += 256) {
        Wa[i] = g_Wa2[i];
        Wc[i] = g_Wc2[i];
    }

    const int tx = threadIdx.x & 15;
    const int ty = threadIdx.x >> 4;
    const int j0 = tx * 4;
    const int r0 = ty * 4;
    const int ntiles = (n_nodes + TN - 1) / TN;

    for (int tile = blockIdx.x; tile < ntiles; tile += gridDim.x) {
        const int base = tile * TN;
        __syncthreads();
        for (int idx = threadIdx.x; idx < (HID / 4) * TN; idx += 256) {
            int cq = idx >> 6;
            int r  = idx & (TN - 1);
            int node = base + r;
            float4 v = make_float4(0.f, 0.f, 0.f, 0.f);
            if (node < n_nodes) v = *(const float4*)(h + (size_t)node * HID + cq * 4);
            hst[(cq * 4 + 0) * TN + r] = v.x;
            hst[(cq * 4 + 1) * TN + r] = v.y;
            hst[(cq * 4 + 2) * TN + r] = v.z;
            hst[(cq * 4 + 3) * TN + r] = v.w;
        }
        __syncthreads();

        u64 aP[4][2], aQ[4][2];
        #pragma unroll
        for (int j = 0; j < 4; j++) {
            aP[j][0] = aP[j][1] = 0ULL;
            aQ[j][0] = aQ[j][1] = 0ULL;
        }
        #pragma unroll 4
        for (int k = 0; k < HID; k++) {
            ulonglong2 sv = *(const ulonglong2*)(hst + k * TN + r0);
            float4 wa = *(const float4*)(Wa + k * HID + j0);
            float4 wc = *(const float4*)(Wc + k * HID + j0);
            u64 a0 = pk2(wa.x, wa.x), a1 = pk2(wa.y, wa.y),
                a2 = pk2(wa.z, wa.z), a3 = pk2(wa.w, wa.w);
            u64 c0 = pk2(wc.x, wc.x), c1 = pk2(wc.y, wc.y),
                c2 = pk2(wc.z, wc.z), c3 = pk2(wc.w, wc.w);
            ffma2(aP[0][0], a0, sv.x); ffma2(aP[0][1], a0, sv.y);
            ffma2(aP[1][0], a1, sv.x); ffma2(aP[1][1], a1, sv.y);
            ffma2(aP[2][0], a2, sv.x); ffma2(aP[2][1], a2, sv.y);
            ffma2(aP[3][0], a3, sv.x); ffma2(aP[3][1], a3, sv.y);
            ffma2(aQ[0][0], c0, sv.x); ffma2(aQ[0][1], c0, sv.y);
            ffma2(aQ[1][0], c1, sv.x); ffma2(aQ[1][1], c1, sv.y);
            ffma2(aQ[2][0], c2, sv.x); ffma2(aQ[2][1], c2, sv.y);
            ffma2(aQ[3][0], c3, sv.x); ffma2(aQ[3][1], c3, sv.y);
        }
        #pragma unroll
        for (int r = 0; r < 4; r++) {
            int node = base + r0 + r;
            if (node < n_nodes) {
                float4 p, q; float2 c;
                c = up2(aP[0][r >> 1]); p.x = (r & 1) ? c.y : c.x;
                c = up2(aP[1][r >> 1]); p.y = (r & 1) ? c.y : c.x;
                c = up2(aP[2][r >> 1]); p.z = (r & 1) ? c.y : c.x;
                c = up2(aP[3][r >> 1]); p.w = (r & 1) ? c.y : c.x;
                c = up2(aQ[0][r >> 1]); q.x = (r & 1) ? c.y : c.x;
                c = up2(aQ[1][r >> 1]); q.y = (r & 1) ? c.y : c.x;
                c = up2(aQ[2][r >> 1]); q.z = (r & 1) ? c.y : c.x;
                c = up2(aQ[3][r >> 1]); q.w = (r & 1) ? c.y : c.x;
                *(float4*)(g_P + (size_t)node * HID + j0) = p;
                *(float4*)(g_Q + (size_t)node * HID + j0) = q;
            }
        }
    }
}

// ---------------------------------------------------------------------------
// Kernel 2: per-edge  out = relu( P[src] + Q[dst] + e_h@W12 + ext@W2b + b12 )
// ---------------------------------------------------------------------------
#define EDGE_SMEM_FLOATS (4096 + 2048 + 64 + HID * TE + EXT * TE)
#define EDGE_SMEM_BYTES  (EDGE_SMEM_FLOATS * 4 + TE * 2 * 4)

__global__ __launch_bounds__(256) void edge_kernel(
    const float* __restrict__ e_h,
    const float* __restrict__ ext,
    const float* __restrict__ W2,
    const int* __restrict__ src,
    const int* __restrict__ dst,
    float* __restrict__ out,
    int n_edges)
{
    extern __shared__ float sm[];
    float* W12s = sm;
    float* W2bs = W12s + 4096;
    float* b12s = W2bs + 2048;
    float* ehs  = b12s + 64;           // [k][r] stride TE
    float* exts = ehs + HID * TE;      // [k][r] stride TE
    int*   srcs = (int*)(exts + EXT * TE);
    int*   dsts = srcs + TE;

    for (int i = threadIdx.x; i < HID * HID; i += 256) W12s[i] = g_W12[i];
    for (int i = threadIdx.x; i < EXT * HID; i += 256) W2bs[i] = W2[HID * HID + i];
    if (threadIdx.x < HID) b12s[threadIdx.x] = g_b12[threadIdx.x];

    const int tx = threadIdx.x & 15;
    const int ty = threadIdx.x >> 4;
    const int j0 = tx * 4;
    const int r0 = ty * 4;
    const int ntiles = (n_edges + TE - 1) / TE;

    for (int tile = blockIdx.x; tile < ntiles; tile += gridDim.x) {
        const int base = tile * TE;
        __syncthreads();

        for (int idx = threadIdx.x; idx < (HID / 4) * TE; idx += 256) {
            int cq = idx >> 6;
            int r  = idx & (TE - 1);
            int e = base + r;
            float4 v = make_float4(0.f, 0.f, 0.f, 0.f);
            if (e < n_edges) v = *(const float4*)(e_h + (size_t)e * HID + cq * 4);
            ehs[(cq * 4 + 0) * TE + r] = v.x;
            ehs[(cq * 4 + 1) * TE + r] = v.y;
            ehs[(cq * 4 + 2) * TE + r] = v.z;
            ehs[(cq * 4 + 3) * TE + r] = v.w;
        }
        for (int idx = threadIdx.x; idx < (EXT / 4) * TE; idx += 256) {
            int cq = idx >> 6;
            int r  = idx & (TE - 1);
            int e = base + r;
            float4 v = make_float4(0.f, 0.f, 0.f, 0.f);
            if (e < n_edges) v = *(const float4*)(ext + (size_t)e * EXT + cq * 4);
            exts[(cq * 4 + 0) * TE + r] = v.x;
            exts[(cq * 4 + 1) * TE + r] = v.y;
            exts[(cq * 4 + 2) * TE + r] = v.z;
            exts[(cq * 4 + 3) * TE + r] = v.w;
        }
        if (threadIdx.x < TE) {
            int e = base + threadIdx.x;
            srcs[threadIdx.x] = (e < n_edges) ? src[e] : 0;
            dsts[threadIdx.x] = (e < n_edges) ? dst[e] : 0;
        }
        __syncthreads();

        float4 bv = *(const float4*)(b12s + j0);
        float4 pq[4];
        #pragma unroll
        for (int r = 0; r < 4; r++) {
            float4 p = *(const float4*)(g_P + (size_t)srcs[r0 + r] * HID + j0);
            float4 q = *(const float4*)(g_Q + (size_t)dsts[r0 + r] * HID + j0);
            pq[r].x = p.x + q.x + bv.x;
            pq[r].y = p.y + q.y + bv.y;
            pq[r].z = p.z + q.z + bv.z;
            pq[r].w = p.w + q.w + bv.w;
        }

        u64 acc[4][2];
        #pragma unroll
        for (int j = 0; j < 4; j++) acc[j][0] = acc[j][1] = 0ULL;

        #pragma unroll 8
        for (int k = 0; k < HID; k++) {
            ulonglong2 sv = *(const ulonglong2*)(ehs + k * TE + r0);
            float4 w = *(const float4*)(W12s + k * HID + j0);
            u64 w0 = pk2(w.x, w.x), w1 = pk2(w.y, w.y),
                w2 = pk2(w.z, w.z), w3 = pk2(w.w, w.w);
            ffma2(acc[0][0], w0, sv.x); ffma2(acc[0][1], w0, sv.y);
            ffma2(acc[1][0], w1, sv.x); ffma2(acc[1][1], w1, sv.y);
            ffma2(acc[2][0], w2, sv.x); ffma2(acc[2][1], w2, sv.y);
            ffma2(acc[3][0], w3, sv.x); ffma2(acc[3][1], w3, sv.y);
        }
        #pragma unroll 8
        for (int k = 0; k < EXT; k++) {
            ulonglong2 sv = *(const ulonglong2*)(exts + k * TE + r0);
            float4 w = *(const float4*)(W2bs + k * HID + j0);
            u64 w0 = pk2(w.x, w.x), w1 = pk2(w.y, w.y),
                w2 = pk2(w.z, w.z), w3 = pk2(w.w, w.w);
            ffma2(acc[0][0], w0, sv.x); ffma2(acc[0][1], w0, sv.y);
            ffma2(acc[1][0], w1, sv.x); ffma2(acc[1][1], w1, sv.y);
            ffma2(acc[2][0], w2, sv.x); ffma2(acc[2][1], w2, sv.y);
            ffma2(acc[3][0], w3, sv.x); ffma2(acc[3][1], w3, sv.y);
        }

        #pragma unroll
        for (int r = 0; r < 4; r++) {
            int e = base + r0 + r;
            if (e < n_edges) {
                float2 c0 = up2(acc[0][r >> 1]);
                float2 c1 = up2(acc[1][r >> 1]);
                float2 c2 = up2(acc[2][r >> 1]);
                float2 c3 = up2(acc[3][r >> 1]);
                float4 o;
                o.x = fmaxf(((r & 1) ? c0.y : c0.x) + pq[r].x, 0.f);
                o.y = fmaxf(((r & 1) ? c1.y : c1.x) + pq[r].y, 0.f);
                o.z = fmaxf(((r & 1) ? c2.y : c2.x) + pq[r].z, 0.f);
                o.w = fmaxf(((r & 1) ? c3.y : c3.x) + pq[r].w, 0.f);
                *(float4*)(out + (size_t)e * HID + j0) = o;
            }
        }
    }
}

// ---------------------------------------------------------------------------
extern "C" void kernel_launch(void* const* d_in, const int* in_sizes, int n_in,
                              void* d_out, int out_size)
{
    const float* h   = (const float*)d_in[0];
    const float* e_h = (const float*)d_in[1];
    const float* ext = (const float*)d_in[2];
    const float* W1  = (const float*)d_in[3];
    const float* b1  = (const float*)d_in[4];
    const float* W2  = (const float*)d_in[5];
    const float* b2  = (const float*)d_in[6];
    const int*   src = (const int*)d_in[7];
    const int*   dst = (const int*)d_in[8];
    float* out = (float*)d_out;

    int n_nodes = in_sizes[0] / HID;
    int n_edges = in_sizes[7];

    cudaFuncSetAttribute(node_pre, cudaFuncAttributeMaxDynamicSharedMemorySize,
                         NODE_SMEM_BYTES);
    cudaFuncSetAttribute(edge_kernel, cudaFuncAttributeMaxDynamicSharedMemorySize,
                         EDGE_SMEM_BYTES);

    combo_kernel<<<13, 256>>>(W1, b1, W2, b2);

    int node_tiles = (n_nodes + TN - 1) / TN;
    int grid1 = node_tiles < 592 ? node_tiles : 592;
    node_pre<<<grid1, 256, NODE_SMEM_BYTES>>>(h, n_nodes);

    int edge_tiles = (n_edges + TE - 1) / TE;
    int grid2 = edge_tiles < 592 ? edge_tiles : 592;
    edge_kernel<<<grid2, 256, EDGE_SMEM_BYTES>>>(e_h, ext, W2, src, dst, out,
                                                 n_edges);
}